// round 3
// baseline (speedup 1.0000x reference)
#include <cuda_runtime.h>
#include <math.h>

// ---------------- problem constants ----------------
#define HH 59
#define WWD 59
#define C_IN 2048
#define MIDC 512
#define NB 4
#define OHH 30
#define OWW 30
#define PPX 900          // OHH*OWW
#define MP 3600          // NB*PPX
#define MMC 3481         // 59*59 mask channels / spatial
#define HALF 29          // (59-1)/2

// ---------------- scratch (device globals; no allocs allowed) ----------------
__device__ float g_xs [MP * C_IN];    // subsampled input, pixel-major [np][c]
__device__ float g_xcd[MP * 1024];    // xc (0..511) | xd (512..1023) per row
__device__ float g_z  [MP * 1024];    // zc | zd
__device__ float g_yc [MP * MMC];     // collect logits  [np][3481]
__device__ float g_yd [MP * MMC];     // distribute logits
__device__ float g_Ac [NB * PPX * PPX]; // softmaxed attention, [n][r][q]
__device__ float g_Ad [NB * PPX * PPX];
__device__ float g_agg[MP * 1024];    // aggregated features [np][1024]
__device__ float g_xpt[C_IN * MP];    // projected, channel-major [c][np]
__device__ float g_s1[1024], g_t1[1024];
__device__ float g_s2[1024], g_t2[1024];
__device__ float g_s3[2048], g_t3[2048];

// ---------------- BN fold ----------------
__device__ __forceinline__ void bnfold(const float* p, int C, int i, float* s, float* t) {
    float g = p[i], b = p[C + i], m = p[2 * C + i], v = p[3 * C + i];
    float sc = g * rsqrtf(v + 1e-5f);
    s[0] = sc; t[0] = b - m * sc;
}

__global__ void bnprep(const float* rbn, const float* rpbn, const float* abn,
                       const float* apbn, const float* pjbn) {
    int i = blockIdx.x * 256 + threadIdx.x;
    if (i < 512) {
        bnfold(rbn,  512, i, &g_s1[i],       &g_t1[i]);
        bnfold(rpbn, 512, i, &g_s1[512 + i], &g_t1[512 + i]);
        bnfold(abn,  512, i, &g_s2[i],       &g_t2[i]);
        bnfold(apbn, 512, i, &g_s2[512 + i], &g_t2[512 + i]);
    }
    if (i < 2048) {
        bnfold(pjbn, 2048, i, &g_s3[i], &g_t3[i]);
    }
}

// ---------------- subsample + transpose: x[n][c][2i][2j] -> xs[n*900+p][c] ----------------
__global__ void gather_sub(const float* __restrict__ x) {
    // grid: (NB*OHH, C_IN/32), block 256; tile covers 32 channels x 30 out-cols
    int nph = blockIdx.x;
    int n = nph / OHH, ph = nph % OHH;
    int c0 = blockIdx.y * 32;
    __shared__ float tile[32][31];
    int t = threadIdx.x;
    for (int e = t; e < 960; e += 256) {
        int cl = e / 30, pw = e % 30;
        tile[cl][pw] = x[((size_t)(n * C_IN + c0 + cl) * HH + 2 * ph) * WWD + 2 * pw];
    }
    __syncthreads();
    for (int e = t; e < 960; e += 256) {
        int pw = e / 32, cl = e % 32;
        g_xs[(size_t)(n * PPX + ph * OWW + pw) * C_IN + c0 + cl] = tile[cl][pw];
    }
}

// ---------------- SGEMM core: C[M][N] = A[M][K] * op(B), NT (B=[N][K]) or NN (B=[K][N]) ----------------
// EPI: 0 none, 1 relu(v*sc[col]+bi[col]), 2 relu(v*sc[row]+bi[row])
template <int EPI, bool BT>
__device__ __forceinline__ void sgemm_core(
    const float* __restrict__ A, int lda,
    const float* __restrict__ B, int ldb,
    float* __restrict__ C, int ldc,
    int M, int N, int K,
    const float* __restrict__ sc, const float* __restrict__ bi)
{
    constexpr int BM = 128, BN = 64, BK = 16;
    __shared__ float As[BK][BM];
    __shared__ float Bs[BK][BN];
    int bm = blockIdx.y * BM, bn = blockIdx.x * BN;
    int tid = threadIdx.x;
    int tm = (tid / 16) * 8;   // 0..120
    int tn = (tid % 16) * 4;   // 0..60
    float acc[8][4];
#pragma unroll
    for (int i = 0; i < 8; i++)
#pragma unroll
        for (int j = 0; j < 4; j++) acc[i][j] = 0.f;

    for (int k0 = 0; k0 < K; k0 += BK) {
        // load A tile: 128 rows x 16 k; 2 threads/row, 8 k each (2048 = 256*8)
        {
            int row = tid >> 1;
            int kq = (tid & 1) * 8;
            int gm = bm + row;
#pragma unroll
            for (int i = 0; i < 8; i++) {
                int gk = k0 + kq + i;
                As[kq + i][row] = (gm < M && gk < K) ? A[(size_t)gm * lda + gk] : 0.f;
            }
        }
        if (BT) {
            // B is [N][K]: 64 rows x 16 k; 4 threads/row, 4 k each (1024 = 256*4)
            int row = tid >> 2;
            int kq = (tid & 3) * 4;
            int gn = bn + row;
#pragma unroll
            for (int i = 0; i < 4; i++) {
                int gk = k0 + kq + i;
                Bs[kq + i][row] = (gn < N && gk < K) ? B[(size_t)gn * ldb + gk] : 0.f;
            }
        } else {
            // B is [K][N]: 16 k x 64 n (1024 = 256*4)
#pragma unroll
            for (int i = 0; i < 4; i++) {
                int k = (tid >> 6) + i * 4;
                int col = tid & 63;
                int gk = k0 + k, gn = bn + col;
                Bs[k][col] = (gk < K && gn < N) ? B[(size_t)gk * ldb + gn] : 0.f;
            }
        }
        __syncthreads();
#pragma unroll
        for (int kk = 0; kk < BK; kk++) {
            float a[8], b[4];
#pragma unroll
            for (int i = 0; i < 8; i++) a[i] = As[kk][tm + i];
#pragma unroll
            for (int j = 0; j < 4; j++) b[j] = Bs[kk][tn + j];
#pragma unroll
            for (int i = 0; i < 8; i++)
#pragma unroll
                for (int j = 0; j < 4; j++) acc[i][j] = fmaf(a[i], b[j], acc[i][j]);
        }
        __syncthreads();
    }
#pragma unroll
    for (int i = 0; i < 8; i++) {
        int gm = bm + tm + i;
        if (gm >= M) continue;
#pragma unroll
        for (int j = 0; j < 4; j++) {
            int gn = bn + tn + j;
            if (gn >= N) continue;
            float v = acc[i][j];
            if (EPI == 1) v = fmaxf(fmaf(v, sc[gn], bi[gn]), 0.f);
            if (EPI == 2) v = fmaxf(fmaf(v, sc[gm], bi[gm]), 0.f);
            C[(size_t)gm * ldc + gn] = v;
        }
    }
}

template <int EPI, bool BT>
__global__ void sgemm(const float* __restrict__ A, int lda,
                      const float* __restrict__ B, int ldb,
                      float* __restrict__ C, int ldc,
                      int M, int N, int K,
                      const float* __restrict__ sc, const float* __restrict__ bi)
{
    sgemm_core<EPI, BT>(A, lda, B, ldb, C, ldc, M, N, K, sc, bi);
}

// Batched attention aggregation: out[r][c] = sum_q Att[n][r][q] * feat[q][c]
// gridDim.z = 8: z = br*4 + n
__global__ void sgemm_agg() {
    int zb = blockIdx.z;
    int n = zb & 3, br = zb >> 2;
    const float* A = (br ? g_Ad : g_Ac) + (size_t)n * PPX * PPX;
    const float* B = g_xcd + (size_t)n * PPX * 1024 + br * 512;
    float* C = g_agg + (size_t)n * PPX * 1024 + br * 512;
    sgemm_core<0, false>(A, PPX, B, 1024, C, 1024, PPX, MIDC, PPX, nullptr, nullptr);
}

// ---------------- psa_mask gather + softmax ----------------
// collect: M[q,r] = yc[pixel r, chan (qh-rh+29)*59 + (qw-rw+29)]; softmax over q for fixed r.
__global__ void softmax_collect(const float* __restrict__ yc, float* __restrict__ Ao) {
    int nr = blockIdx.x;
    int r = nr % PPX;
    int rh = r / OWW, rw = r % OWW;
    const float* row = yc + (size_t)nr * MMC;
    __shared__ float buf[PPX];
    __shared__ float red[256];
    int t = threadIdx.x;
    float mx = -1e30f;
    for (int q = t; q < PPX; q += 256) {
        int qh = q / OWW, qw = q % OWW;
        float v = row[(qh - rh + HALF) * 59 + (qw - rw + HALF)];
        buf[q] = v;
        mx = fmaxf(mx, v);
    }
    red[t] = mx; __syncthreads();
    for (int s = 128; s > 0; s >>= 1) { if (t < s) red[t] = fmaxf(red[t], red[t + s]); __syncthreads(); }
    mx = red[0]; __syncthreads();
    float sum = 0.f;
    for (int q = t; q < PPX; q += 256) {
        float e = __expf(buf[q] - mx);
        buf[q] = e; sum += e;
    }
    red[t] = sum; __syncthreads();
    for (int s = 128; s > 0; s >>= 1) { if (t < s) red[t] += red[t + s]; __syncthreads(); }
    float inv = 1.f / red[0];
    float* out = Ao + (size_t)nr * PPX;
    for (int q = t; q < PPX; q += 256) out[q] = buf[q] * inv;
}

// distribute: M[q,r] = yd[pixel q, chan (rh-qh+29)*59 + (rw-qw+29)]; softmax over q for fixed r.
__global__ void softmax_distribute(const float* __restrict__ yd, float* __restrict__ Ao) {
    int nr = blockIdx.x;
    int n = nr / PPX, r = nr % PPX;
    int rh = r / OWW, rw = r % OWW;
    __shared__ float buf[PPX];
    __shared__ float red[256];
    int t = threadIdx.x;
    float mx = -1e30f;
    for (int q = t; q < PPX; q += 256) {
        int qh = q / OWW, qw = q % OWW;
        float v = yd[(size_t)(n * PPX + q) * MMC + (rh - qh + HALF) * 59 + (rw - qw + HALF)];
        buf[q] = v;
        mx = fmaxf(mx, v);
    }
    red[t] = mx; __syncthreads();
    for (int s = 128; s > 0; s >>= 1) { if (t < s) red[t] = fmaxf(red[t], red[t + s]); __syncthreads(); }
    mx = red[0]; __syncthreads();
    float sum = 0.f;
    for (int q = t; q < PPX; q += 256) {
        float e = __expf(buf[q] - mx);
        buf[q] = e; sum += e;
    }
    red[t] = sum; __syncthreads();
    for (int s = 128; s > 0; s >>= 1) { if (t < s) red[t] += red[t + s]; __syncthreads(); }
    float inv = 1.f / red[0];
    float* out = Ao + (size_t)nr * PPX;
    for (int q = t; q < PPX; q += 256) out[q] = buf[q] * inv;
}

// ---------------- output assembly ----------------
// channels 0..2047: straight copy of x
__global__ void copy_x(const float* __restrict__ x, float* __restrict__ out) {
    size_t idx = (size_t)blockIdx.x * 256 + threadIdx.x;
    size_t total = (size_t)NB * C_IN * MMC;
    if (idx >= total) return;
    int s = idx % MMC;
    size_t nc = idx / MMC;
    int n = (int)(nc / C_IN), c = (int)(nc % C_IN);
    out[((size_t)(n * 4096 + c)) * MMC + s] = x[idx];
}

// channels 2048..4095: bilinear upsample 30->59 of g_xpt [c][n*900+p]
__global__ void upsample(float* __restrict__ out) {
    size_t idx = (size_t)blockIdx.x * 256 + threadIdx.x;
    size_t total = (size_t)NB * C_IN * MMC;
    if (idx >= total) return;
    int s = idx % MMC;
    size_t nc = idx / MMC;
    int n = (int)(nc / C_IN), c = (int)(nc % C_IN);
    int i = s / 59, j = s % 59;
    float fi = i * 0.5f, fj = j * 0.5f;
    int i0 = min(i >> 1, OHH - 2);
    int j0 = min(j >> 1, OWW - 2);
    float fh = fi - i0, fw = fj - j0;
    int i1 = i0 + 1, j1 = j0 + 1;
    const float* src = g_xpt + (size_t)c * MP + n * PPX;
    float v00 = src[i0 * OWW + j0], v01 = src[i0 * OWW + j1];
    float v10 = src[i1 * OWW + j0], v11 = src[i1 * OWW + j1];
    float v = (1.f - fh) * ((1.f - fw) * v00 + fw * v01)
            + fh * ((1.f - fw) * v10 + fw * v11);
    out[((size_t)(n * 4096 + 2048 + c)) * MMC + s] = v;
}

// ---------------- launch ----------------
extern "C" void kernel_launch(void* const* d_in, const int* in_sizes, int n_in,
                              void* d_out, int out_size) {
    const float* x    = (const float*)d_in[0];
    const float* rw   = (const float*)d_in[1];
    const float* rbn  = (const float*)d_in[2];
    const float* a1w  = (const float*)d_in[3];
    const float* abn  = (const float*)d_in[4];
    const float* a2w  = (const float*)d_in[5];
    const float* rpw  = (const float*)d_in[6];
    const float* rpbn = (const float*)d_in[7];
    const float* ap1w = (const float*)d_in[8];
    const float* apbn = (const float*)d_in[9];
    const float* ap2w = (const float*)d_in[10];
    const float* pjw  = (const float*)d_in[11];
    const float* pjbn = (const float*)d_in[12];
    float* out = (float*)d_out;

    float *xs, *xcd, *z, *yc, *yd, *Ac, *Ad, *agg, *xpt;
    float *s1, *t1, *s2, *t2, *s3, *t3;
    cudaGetSymbolAddress((void**)&xs,  g_xs);
    cudaGetSymbolAddress((void**)&xcd, g_xcd);
    cudaGetSymbolAddress((void**)&z,   g_z);
    cudaGetSymbolAddress((void**)&yc,  g_yc);
    cudaGetSymbolAddress((void**)&yd,  g_yd);
    cudaGetSymbolAddress((void**)&Ac,  g_Ac);
    cudaGetSymbolAddress((void**)&Ad,  g_Ad);
    cudaGetSymbolAddress((void**)&agg, g_agg);
    cudaGetSymbolAddress((void**)&xpt, g_xpt);
    cudaGetSymbolAddress((void**)&s1,  g_s1);
    cudaGetSymbolAddress((void**)&t1,  g_t1);
    cudaGetSymbolAddress((void**)&s2,  g_s2);
    cudaGetSymbolAddress((void**)&t2,  g_t2);
    cudaGetSymbolAddress((void**)&s3,  g_s3);
    cudaGetSymbolAddress((void**)&t3,  g_t3);

    // 1. BN folding
    bnprep<<<8, 256>>>(rbn, rpbn, abn, apbn, pjbn);

    // 2. subsample+transpose input
    gather_sub<<<dim3(NB * OHH, C_IN / 32), 256>>>(x);

    // 3. conv1 (both branches): xs[3600,2048] x W[512,2048]^T -> xcd
    {
        dim3 g(MIDC / 64, (MP + 127) / 128);
        sgemm<1, true><<<g, 256>>>(xs, C_IN, rw,  C_IN, xcd,       1024, MP, MIDC, C_IN, s1,       t1);
        sgemm<1, true><<<g, 256>>>(xs, C_IN, rpw, C_IN, xcd + 512, 1024, MP, MIDC, C_IN, s1 + 512, t1 + 512);
    }

    // 4. attention conv1: xc x a1w^T -> z
    {
        dim3 g(MIDC / 64, (MP + 127) / 128);
        sgemm<1, true><<<g, 256>>>(xcd,       1024, a1w,  MIDC, z,       1024, MP, MIDC, MIDC, s2,       t2);
        sgemm<1, true><<<g, 256>>>(xcd + 512, 1024, ap1w, MIDC, z + 512, 1024, MP, MIDC, MIDC, s2 + 512, t2 + 512);
    }

    // 5. attention conv2 (logits): z x a2w^T -> yc/yd [3600, 3481]
    {
        dim3 g((MMC + 63) / 64, (MP + 127) / 128);
        sgemm<0, true><<<g, 256>>>(z,       1024, a2w,  MIDC, yc, MMC, MP, MMC, MIDC, nullptr, nullptr);
        sgemm<0, true><<<g, 256>>>(z + 512, 1024, ap2w, MIDC, yd, MMC, MP, MMC, MIDC, nullptr, nullptr);
    }

    // 6. psa_mask gather + softmax -> Ac, Ad  [n][r][q]
    softmax_collect<<<MP, 256>>>(yc, Ac);
    softmax_distribute<<<MP, 256>>>(yd, Ad);

    // 7. aggregation (batched over n x branch)
    {
        dim3 g(MIDC / 64, (PPX + 127) / 128, 8);
        sgemm_agg<<<g, 256>>>();
    }

    // 8. projection: pjw[2048,1024] x agg[3600,1024]^T -> xpt [2048][3600], BN+ReLU per row
    {
        dim3 g((MP + 63) / 64, C_IN / 128);
        sgemm<2, true><<<g, 256>>>(pjw, 1024, agg, 1024, xpt, MP, C_IN, MP, 1024, s3, t3);
    }

    // 9. assemble output
    {
        size_t total = (size_t)NB * C_IN * MMC;
        int blocks = (int)((total + 255) / 256);
        copy_x<<<blocks, 256>>>(x, out);
        upsample<<<blocks, 256>>>(out);
    }
}

// round 4
// speedup vs baseline: 1.8367x; 1.8367x over previous
#include <cuda_runtime.h>
#include <math.h>
#include <stdint.h>

// ---------------- problem constants ----------------
#define HH 59
#define WWD 59
#define C_IN 2048
#define MIDC 512
#define NB 4
#define OHH 30
#define OWW 30
#define PPX 900          // OHH*OWW
#define MP 3600          // NB*PPX
#define MMC 3481         // 59*59 mask channels / spatial
#define HALF 29          // (59-1)/2

// ---------------- scratch (device globals; no allocs allowed) ----------------
__device__ float g_xs [MP * C_IN];    // subsampled input, pixel-major [np][c]
__device__ float g_xcd[MP * 1024];    // xc (0..511) | xd (512..1023) per row
__device__ float g_z  [MP * 1024];    // zc | zd
__device__ float g_yc [MP * MMC];     // collect logits  [np][3481]
__device__ float g_yd [MP * MMC];     // distribute logits
__device__ float g_Ac [NB * PPX * PPX]; // softmaxed attention, [n][r][q]
__device__ float g_Ad [NB * PPX * PPX];
__device__ float g_agg[MP * 1024];    // aggregated features [np][1024]
__device__ float g_xpt[C_IN * MP];    // projected, channel-major [c][np]
__device__ float g_s1[1024], g_t1[1024];
__device__ float g_s2[1024], g_t2[1024];
__device__ float g_s3[2048], g_t3[2048];

// ---------------- BN fold ----------------
__device__ __forceinline__ void bnfold(const float* p, int C, int i, float* s, float* t) {
    float g = p[i], b = p[C + i], m = p[2 * C + i], v = p[3 * C + i];
    float sc = g * rsqrtf(v + 1e-5f);
    s[0] = sc; t[0] = b - m * sc;
}

__global__ void bnprep(const float* rbn, const float* rpbn, const float* abn,
                       const float* apbn, const float* pjbn) {
    int i = blockIdx.x * 256 + threadIdx.x;
    if (i < 512) {
        bnfold(rbn,  512, i, &g_s1[i],       &g_t1[i]);
        bnfold(rpbn, 512, i, &g_s1[512 + i], &g_t1[512 + i]);
        bnfold(abn,  512, i, &g_s2[i],       &g_t2[i]);
        bnfold(apbn, 512, i, &g_s2[512 + i], &g_t2[512 + i]);
    }
    if (i < 2048) {
        bnfold(pjbn, 2048, i, &g_s3[i], &g_t3[i]);
    }
}

// ---------------- subsample + transpose: x[n][c][2i][2j] -> xs[n*900+p][c] ----------------
__global__ void gather_sub(const float* __restrict__ x) {
    int nph = blockIdx.x;
    int n = nph / OHH, ph = nph % OHH;
    int c0 = blockIdx.y * 32;
    __shared__ float tile[32][31];
    int t = threadIdx.x;
    for (int e = t; e < 960; e += 256) {
        int cl = e / 30, pw = e % 30;
        tile[cl][pw] = x[((size_t)(n * C_IN + c0 + cl) * HH + 2 * ph) * WWD + 2 * pw];
    }
    __syncthreads();
    for (int e = t; e < 960; e += 256) {
        int pw = e / 32, cl = e % 32;
        g_xs[(size_t)(n * PPX + ph * OWW + pw) * C_IN + c0 + cl] = tile[cl][pw];
    }
}

// ---------------- TF32 tensor-core GEMM ----------------
// C[M][N] = A[M][K] * op(B);  BT: B[N][K] (NT GEMM), else B[K][N] (NN).
// Block tile 128x64x32, 8 warps (4 m x 2 n), warp tile 32x32 = 2x4 m16n8k8 frags.
// Smem k-major with stride 136/72 (=8 mod 32) + XOR swizzle -> conflict-free
// for both transposed stores and fragment loads.

__device__ __forceinline__ float tf32r(float x) {
    unsigned u;
    asm("cvt.rna.tf32.f32 %0, %1;" : "=r"(u) : "f"(x));
    return __uint_as_float(u);
}

__device__ __forceinline__ void mma8(float* c, const unsigned* a, unsigned b0, unsigned b1) {
    asm volatile(
        "mma.sync.aligned.m16n8k8.row.col.f32.tf32.tf32.f32 "
        "{%0,%1,%2,%3}, {%4,%5,%6,%7}, {%8,%9}, {%0,%1,%2,%3};\n"
        : "+f"(c[0]), "+f"(c[1]), "+f"(c[2]), "+f"(c[3])
        : "r"(a[0]), "r"(a[1]), "r"(a[2]), "r"(a[3]), "r"(b0), "r"(b1));
}

#define SWA(k, m) ((k) * 136 + ((m) ^ ((((k) >> 2) & 7) << 2)))
#define SWB(k, n) ((k) * 72  + ((n) ^ ((((k) >> 2) & 7) << 2)))

// EPI: 0 none, 1 relu(v*sc[col]+bi[col]), 2 relu(v*sc[row]+bi[row])
template <int EPI, bool BT>
__device__ __forceinline__ void tgemm_core(
    const float* __restrict__ A, int lda,
    const float* __restrict__ B, int ldb,
    float* __restrict__ C, int ldc,
    int M, int N, int K,
    const float* __restrict__ sc, const float* __restrict__ bi)
{
    constexpr int BM = 128, BN = 64, BK = 32;
    __shared__ float As[BK * 136];
    __shared__ float Bs[BK * 72];
    int tid = threadIdx.x;
    int lane = tid & 31, wid = tid >> 5;
    int wm = wid & 3, wn = wid >> 2;          // 4 x 2 warp grid
    int bm = blockIdx.y * BM, bn = blockIdx.x * BN;
    int g8 = lane >> 2, t4 = lane & 3;

    float acc[2][4][4];
#pragma unroll
    for (int i = 0; i < 2; i++)
#pragma unroll
        for (int j = 0; j < 4; j++)
#pragma unroll
            for (int q = 0; q < 4; q++) acc[i][j][q] = 0.f;

    const bool cleanM = (bm + BM <= M);
    const bool cleanN = (bn + BN <= N);

    for (int k0 = 0; k0 < K; k0 += BK) {
        const bool cleanK = (k0 + BK <= K);
        // ---- load A tile: BM x BK, store transposed+swizzled ----
#pragma unroll
        for (int i = 0; i < 4; i++) {
            int fid = tid + i * 256;
            int row = fid >> 3, kq = (fid & 7) * 4;
            int gm = bm + row, gk = k0 + kq;
            float4 v;
            if (cleanM && cleanK) {
                v = *(const float4*)(A + (size_t)gm * lda + gk);
            } else {
                v.x = (gm < M && gk     < K) ? A[(size_t)gm * lda + gk    ] : 0.f;
                v.y = (gm < M && gk + 1 < K) ? A[(size_t)gm * lda + gk + 1] : 0.f;
                v.z = (gm < M && gk + 2 < K) ? A[(size_t)gm * lda + gk + 2] : 0.f;
                v.w = (gm < M && gk + 3 < K) ? A[(size_t)gm * lda + gk + 3] : 0.f;
            }
            As[SWA(kq + 0, row)] = tf32r(v.x);
            As[SWA(kq + 1, row)] = tf32r(v.y);
            As[SWA(kq + 2, row)] = tf32r(v.z);
            As[SWA(kq + 3, row)] = tf32r(v.w);
        }
        // ---- load B tile -> Bs[k][n] ----
        if (BT) {
#pragma unroll
            for (int i = 0; i < 2; i++) {
                int fid = tid + i * 256;
                int row = fid >> 3, kq = (fid & 7) * 4;   // row = n
                int gn = bn + row, gk = k0 + kq;
                float4 v;
                if (cleanN && cleanK) {
                    v = *(const float4*)(B + (size_t)gn * ldb + gk);
                } else {
                    v.x = (gn < N && gk     < K) ? B[(size_t)gn * ldb + gk    ] : 0.f;
                    v.y = (gn < N && gk + 1 < K) ? B[(size_t)gn * ldb + gk + 1] : 0.f;
                    v.z = (gn < N && gk + 2 < K) ? B[(size_t)gn * ldb + gk + 2] : 0.f;
                    v.w = (gn < N && gk + 3 < K) ? B[(size_t)gn * ldb + gk + 3] : 0.f;
                }
                Bs[SWB(kq + 0, row)] = tf32r(v.x);
                Bs[SWB(kq + 1, row)] = tf32r(v.y);
                Bs[SWB(kq + 2, row)] = tf32r(v.z);
                Bs[SWB(kq + 3, row)] = tf32r(v.w);
            }
        } else {
#pragma unroll
            for (int i = 0; i < 2; i++) {
                int fid = tid + i * 256;
                int kr = fid >> 4, nq = (fid & 15) * 4;
                int gk = k0 + kr, gn = bn + nq;
                float4 v;
                if (cleanN && cleanK) {
                    v = *(const float4*)(B + (size_t)gk * ldb + gn);
                } else {
                    v.x = (gk < K && gn     < N) ? B[(size_t)gk * ldb + gn    ] : 0.f;
                    v.y = (gk < K && gn + 1 < N) ? B[(size_t)gk * ldb + gn + 1] : 0.f;
                    v.z = (gk < K && gn + 2 < N) ? B[(size_t)gk * ldb + gn + 2] : 0.f;
                    v.w = (gk < K && gn + 3 < N) ? B[(size_t)gk * ldb + gn + 3] : 0.f;
                }
                int cc = (kr >> 2) & 7;
                float4 w = make_float4(tf32r(v.x), tf32r(v.y), tf32r(v.z), tf32r(v.w));
                *(float4*)&Bs[kr * 72 + (nq ^ (cc << 2))] = w;
            }
        }
        __syncthreads();

        // ---- compute 4 k-steps of 8 ----
#pragma unroll
        for (int kk = 0; kk < 4; kk++) {
            int kb = kk * 8;
            unsigned a[2][4];
#pragma unroll
            for (int fm = 0; fm < 2; fm++) {
                int m0 = wm * 32 + fm * 16;
                a[fm][0] = __float_as_uint(As[SWA(kb + t4,     m0 + g8)]);
                a[fm][1] = __float_as_uint(As[SWA(kb + t4,     m0 + 8 + g8)]);
                a[fm][2] = __float_as_uint(As[SWA(kb + t4 + 4, m0 + g8)]);
                a[fm][3] = __float_as_uint(As[SWA(kb + t4 + 4, m0 + 8 + g8)]);
            }
#pragma unroll
            for (int fn = 0; fn < 4; fn++) {
                int n0 = wn * 32 + fn * 8;
                unsigned b0 = __float_as_uint(Bs[SWB(kb + t4,     n0 + g8)]);
                unsigned b1 = __float_as_uint(Bs[SWB(kb + t4 + 4, n0 + g8)]);
                mma8(acc[0][fn], a[0], b0, b1);
                mma8(acc[1][fn], a[1], b0, b1);
            }
        }
        __syncthreads();
    }

    // ---- epilogue ----
#pragma unroll
    for (int fm = 0; fm < 2; fm++) {
#pragma unroll
        for (int fn = 0; fn < 4; fn++) {
            int gm0 = bm + wm * 32 + fm * 16 + g8;
            int gn0 = bn + wn * 32 + fn * 8 + 2 * t4;
#pragma unroll
            for (int h = 0; h < 2; h++) {          // h: row group (+0 / +8)
                int gm = gm0 + h * 8;
                if (gm >= M) continue;
#pragma unroll
                for (int q = 0; q < 2; q++) {      // q: col (+0 / +1)
                    int gn = gn0 + q;
                    if (gn >= N) continue;
                    float v = acc[fm][fn][h * 2 + q];
                    if (EPI == 1) v = fmaxf(fmaf(v, sc[gn], bi[gn]), 0.f);
                    if (EPI == 2) v = fmaxf(fmaf(v, sc[gm], bi[gm]), 0.f);
                    C[(size_t)gm * ldc + gn] = v;
                }
            }
        }
    }
}

template <int EPI, bool BT>
__global__ void __launch_bounds__(256) tgemm(
    const float* __restrict__ A, int lda,
    const float* __restrict__ B, int ldb,
    float* __restrict__ C, int ldc,
    int M, int N, int K,
    const float* __restrict__ sc, const float* __restrict__ bi)
{
    tgemm_core<EPI, BT>(A, lda, B, ldb, C, ldc, M, N, K, sc, bi);
}

// Batched attention aggregation: out[r][c] = sum_q Att[n][r][q] * feat[q][c]
// gridDim.z = 8: z = br*4 + n
__global__ void __launch_bounds__(256) tgemm_agg() {
    int zb = blockIdx.z;
    int n = zb & 3, br = zb >> 2;
    const float* A = (br ? g_Ad : g_Ac) + (size_t)n * PPX * PPX;
    const float* B = g_xcd + (size_t)n * PPX * 1024 + br * 512;
    float* C = g_agg + (size_t)n * PPX * 1024 + br * 512;
    tgemm_core<0, false>(A, PPX, B, 1024, C, 1024, PPX, MIDC, PPX, nullptr, nullptr);
}

// ---------------- psa_mask gather + softmax ----------------
__global__ void softmax_collect(const float* __restrict__ yc, float* __restrict__ Ao) {
    int nr = blockIdx.x;
    int r = nr % PPX;
    int rh = r / OWW, rw = r % OWW;
    const float* row = yc + (size_t)nr * MMC;
    __shared__ float buf[PPX];
    __shared__ float red[256];
    int t = threadIdx.x;
    float mx = -1e30f;
    for (int q = t; q < PPX; q += 256) {
        int qh = q / OWW, qw = q % OWW;
        float v = row[(qh - rh + HALF) * 59 + (qw - rw + HALF)];
        buf[q] = v;
        mx = fmaxf(mx, v);
    }
    red[t] = mx; __syncthreads();
    for (int s = 128; s > 0; s >>= 1) { if (t < s) red[t] = fmaxf(red[t], red[t + s]); __syncthreads(); }
    mx = red[0]; __syncthreads();
    float sum = 0.f;
    for (int q = t; q < PPX; q += 256) {
        float e = __expf(buf[q] - mx);
        buf[q] = e; sum += e;
    }
    red[t] = sum; __syncthreads();
    for (int s = 128; s > 0; s >>= 1) { if (t < s) red[t] += red[t + s]; __syncthreads(); }
    float inv = 1.f / red[0];
    float* out = Ao + (size_t)nr * PPX;
    for (int q = t; q < PPX; q += 256) out[q] = buf[q] * inv;
}

__global__ void softmax_distribute(const float* __restrict__ yd, float* __restrict__ Ao) {
    int nr = blockIdx.x;
    int n = nr / PPX, r = nr % PPX;
    int rh = r / OWW, rw = r % OWW;
    __shared__ float buf[PPX];
    __shared__ float red[256];
    int t = threadIdx.x;
    float mx = -1e30f;
    for (int q = t; q < PPX; q += 256) {
        int qh = q / OWW, qw = q % OWW;
        float v = yd[(size_t)(n * PPX + q) * MMC + (rh - qh + HALF) * 59 + (rw - qw + HALF)];
        buf[q] = v;
        mx = fmaxf(mx, v);
    }
    red[t] = mx; __syncthreads();
    for (int s = 128; s > 0; s >>= 1) { if (t < s) red[t] = fmaxf(red[t], red[t + s]); __syncthreads(); }
    mx = red[0]; __syncthreads();
    float sum = 0.f;
    for (int q = t; q < PPX; q += 256) {
        float e = __expf(buf[q] - mx);
        buf[q] = e; sum += e;
    }
    red[t] = sum; __syncthreads();
    for (int s = 128; s > 0; s >>= 1) { if (t < s) red[t] += red[t + s]; __syncthreads(); }
    float inv = 1.f / red[0];
    float* out = Ao + (size_t)nr * PPX;
    for (int q = t; q < PPX; q += 256) out[q] = buf[q] * inv;
}

// ---------------- output assembly ----------------
__global__ void copy_x(const float* __restrict__ x, float* __restrict__ out) {
    size_t idx = (size_t)blockIdx.x * 256 + threadIdx.x;
    size_t total = (size_t)NB * C_IN * MMC;
    if (idx >= total) return;
    int s = idx % MMC;
    size_t nc = idx / MMC;
    int n = (int)(nc / C_IN), c = (int)(nc % C_IN);
    out[((size_t)(n * 4096 + c)) * MMC + s] = x[idx];
}

__global__ void upsample(float* __restrict__ out) {
    size_t idx = (size_t)blockIdx.x * 256 + threadIdx.x;
    size_t total = (size_t)NB * C_IN * MMC;
    if (idx >= total) return;
    int s = idx % MMC;
    size_t nc = idx / MMC;
    int n = (int)(nc / C_IN), c = (int)(nc % C_IN);
    int i = s / 59, j = s % 59;
    float fi = i * 0.5f, fj = j * 0.5f;
    int i0 = min(i >> 1, OHH - 2);
    int j0 = min(j >> 1, OWW - 2);
    float fh = fi - i0, fw = fj - j0;
    int i1 = i0 + 1, j1 = j0 + 1;
    const float* src = g_xpt + (size_t)c * MP + n * PPX;
    float v00 = src[i0 * OWW + j0], v01 = src[i0 * OWW + j1];
    float v10 = src[i1 * OWW + j0], v11 = src[i1 * OWW + j1];
    float v = (1.f - fh) * ((1.f - fw) * v00 + fw * v01)
            + fh * ((1.f - fw) * v10 + fw * v11);
    out[((size_t)(n * 4096 + 2048 + c)) * MMC + s] = v;
}

// ---------------- launch ----------------
extern "C" void kernel_launch(void* const* d_in, const int* in_sizes, int n_in,
                              void* d_out, int out_size) {
    const float* x    = (const float*)d_in[0];
    const float* rw   = (const float*)d_in[1];
    const float* rbn  = (const float*)d_in[2];
    const float* a1w  = (const float*)d_in[3];
    const float* abn  = (const float*)d_in[4];
    const float* a2w  = (const float*)d_in[5];
    const float* rpw  = (const float*)d_in[6];
    const float* rpbn = (const float*)d_in[7];
    const float* ap1w = (const float*)d_in[8];
    const float* apbn = (const float*)d_in[9];
    const float* ap2w = (const float*)d_in[10];
    const float* pjw  = (const float*)d_in[11];
    const float* pjbn = (const float*)d_in[12];
    float* out = (float*)d_out;

    float *xs, *xcd, *z, *yc, *yd, *Ac, *Ad, *agg, *xpt;
    float *s1, *t1, *s2, *t2, *s3, *t3;
    cudaGetSymbolAddress((void**)&xs,  g_xs);
    cudaGetSymbolAddress((void**)&xcd, g_xcd);
    cudaGetSymbolAddress((void**)&z,   g_z);
    cudaGetSymbolAddress((void**)&yc,  g_yc);
    cudaGetSymbolAddress((void**)&yd,  g_yd);
    cudaGetSymbolAddress((void**)&Ac,  g_Ac);
    cudaGetSymbolAddress((void**)&Ad,  g_Ad);
    cudaGetSymbolAddress((void**)&agg, g_agg);
    cudaGetSymbolAddress((void**)&xpt, g_xpt);
    cudaGetSymbolAddress((void**)&s1,  g_s1);
    cudaGetSymbolAddress((void**)&t1,  g_t1);
    cudaGetSymbolAddress((void**)&s2,  g_s2);
    cudaGetSymbolAddress((void**)&t2,  g_t2);
    cudaGetSymbolAddress((void**)&s3,  g_s3);
    cudaGetSymbolAddress((void**)&t3,  g_t3);

    // 1. BN folding
    bnprep<<<8, 256>>>(rbn, rpbn, abn, apbn, pjbn);

    // 2. subsample+transpose input
    gather_sub<<<dim3(NB * OHH, C_IN / 32), 256>>>(x);

    // 3. conv1 (both branches): xs[3600,2048] x W[512,2048]^T -> xcd
    {
        dim3 g(MIDC / 64, (MP + 127) / 128);
        tgemm<1, true><<<g, 256>>>(xs, C_IN, rw,  C_IN, xcd,       1024, MP, MIDC, C_IN, s1,       t1);
        tgemm<1, true><<<g, 256>>>(xs, C_IN, rpw, C_IN, xcd + 512, 1024, MP, MIDC, C_IN, s1 + 512, t1 + 512);
    }

    // 4. attention conv1: xc x a1w^T -> z
    {
        dim3 g(MIDC / 64, (MP + 127) / 128);
        tgemm<1, true><<<g, 256>>>(xcd,       1024, a1w,  MIDC, z,       1024, MP, MIDC, MIDC, s2,       t2);
        tgemm<1, true><<<g, 256>>>(xcd + 512, 1024, ap1w, MIDC, z + 512, 1024, MP, MIDC, MIDC, s2 + 512, t2 + 512);
    }

    // 5. attention conv2 (logits): z x a2w^T -> yc/yd [3600, 3481]
    {
        dim3 g((MMC + 63) / 64, (MP + 127) / 128);
        tgemm<0, true><<<g, 256>>>(z,       1024, a2w,  MIDC, yc, MMC, MP, MMC, MIDC, nullptr, nullptr);
        tgemm<0, true><<<g, 256>>>(z + 512, 1024, ap2w, MIDC, yd, MMC, MP, MMC, MIDC, nullptr, nullptr);
    }

    // 6. psa_mask gather + softmax -> Ac, Ad  [n][r][q]
    softmax_collect<<<MP, 256>>>(yc, Ac);
    softmax_distribute<<<MP, 256>>>(yd, Ad);

    // 7. aggregation (batched over n x branch): NN GEMM, K=900
    {
        dim3 g(MIDC / 64, (PPX + 127) / 128, 8);
        tgemm_agg<<<g, 256>>>();
    }

    // 8. projection: pjw[2048,1024] x agg[3600,1024]^T -> xpt [2048][3600]
    {
        dim3 g((MP + 63) / 64, C_IN / 128);
        tgemm<2, true><<<g, 256>>>(pjw, 1024, agg, 1024, xpt, MP, C_IN, MP, 1024, s3, t3);
    }

    // 9. assemble output
    {
        size_t total = (size_t)NB * C_IN * MMC;
        int blocks = (int)((total + 255) / 256);
        copy_x<<<blocks, 256>>>(x, out);
        upsample<<<blocks, 256>>>(out);
    }
}

// round 5
// speedup vs baseline: 3.5137x; 1.9130x over previous
#include <cuda_runtime.h>
#include <math.h>
#include <stdint.h>

// ---------------- problem constants ----------------
#define HH 59
#define WWD 59
#define C_IN 2048
#define MIDC 512
#define NB 4
#define OHH 30
#define OWW 30
#define PPX 900          // OHH*OWW
#define MP 3600          // NB*PPX
#define MMC 3481         // 59*59 mask channels / spatial
#define HALF 29          // (59-1)/2

// ---------------- scratch (device globals; no allocs allowed) ----------------
__device__ float g_xs [MP * C_IN];
__device__ float g_xcd[MP * 1024];
__device__ float g_z  [MP * 1024];
__device__ float g_yc [MP * MMC];
__device__ float g_yd [MP * MMC];
__device__ float g_Ac [NB * PPX * PPX];
__device__ float g_Ad [NB * PPX * PPX];
__device__ float g_agg[MP * 1024];
__device__ float g_xpt[C_IN * MP];
__device__ float g_s1[1024], g_t1[1024];
__device__ float g_s2[1024], g_t2[1024];
__device__ float g_s3[2048], g_t3[2048];

// ---------------- BN fold ----------------
__device__ __forceinline__ void bnfold(const float* p, int C, int i, float* s, float* t) {
    float g = p[i], b = p[C + i], m = p[2 * C + i], v = p[3 * C + i];
    float sc = g * rsqrtf(v + 1e-5f);
    s[0] = sc; t[0] = b - m * sc;
}

__global__ void bnprep(const float* rbn, const float* rpbn, const float* abn,
                       const float* apbn, const float* pjbn) {
    int i = blockIdx.x * 256 + threadIdx.x;
    if (i < 512) {
        bnfold(rbn,  512, i, &g_s1[i],       &g_t1[i]);
        bnfold(rpbn, 512, i, &g_s1[512 + i], &g_t1[512 + i]);
        bnfold(abn,  512, i, &g_s2[i],       &g_t2[i]);
        bnfold(apbn, 512, i, &g_s2[512 + i], &g_t2[512 + i]);
    }
    if (i < 2048) {
        bnfold(pjbn, 2048, i, &g_s3[i], &g_t3[i]);
    }
}

// ---------------- subsample + transpose ----------------
__global__ void gather_sub(const float* __restrict__ x) {
    int nph = blockIdx.x;
    int n = nph / OHH, ph = nph % OHH;
    int c0 = blockIdx.y * 32;
    __shared__ float tile[32][31];
    int t = threadIdx.x;
    for (int e = t; e < 960; e += 256) {
        int cl = e / 30, pw = e % 30;
        tile[cl][pw] = x[((size_t)(n * C_IN + c0 + cl) * HH + 2 * ph) * WWD + 2 * pw];
    }
    __syncthreads();
    for (int e = t; e < 960; e += 256) {
        int pw = e / 32, cl = e % 32;
        g_xs[(size_t)(n * PPX + ph * OWW + pw) * C_IN + c0 + cl] = tile[cl][pw];
    }
}

// ---------------- TF32 tensor-core GEMM, cp.async 3-stage pipeline ----------------
// Block tile 128x64x32, 8 warps (4m x 2n), warp tile 32x32 (2x4 m16n8k8).
// Smem row-major: As[m][k] stride 36, Bs NT [n][k] stride 36, NN [k][n] stride 72.
// fp32 stored raw; MMA truncates to tf32 in hardware.

#define ASTRIDE 36
#define ASZ (128 * 36)      // floats per stage
#define BSZ 2304            // 64*36 (NT)  == 32*72 (NN)
#define STAGES 3
#define SMEM_BYTES ((STAGES * (ASZ + BSZ)) * 4)

__device__ __forceinline__ void mma8(float* c, const unsigned* a, unsigned b0, unsigned b1) {
    asm volatile(
        "mma.sync.aligned.m16n8k8.row.col.f32.tf32.tf32.f32 "
        "{%0,%1,%2,%3}, {%4,%5,%6,%7}, {%8,%9}, {%0,%1,%2,%3};\n"
        : "+f"(c[0]), "+f"(c[1]), "+f"(c[2]), "+f"(c[3])
        : "r"(a[0]), "r"(a[1]), "r"(a[2]), "r"(a[3]), "r"(b0), "r"(b1));
}

__device__ __forceinline__ void cp16(float* dst, const float* src, bool pred) {
    uint32_t d = (uint32_t)__cvta_generic_to_shared(dst);
    asm volatile("cp.async.cg.shared.global [%0], [%1], 16, %2;\n"
                 :: "r"(d), "l"(src), "r"(pred ? 16 : 0));
}

__device__ __forceinline__ void loadA(float* As, const float* A, int lda,
                                      int bm, int k0, int M, int K, int tid) {
#pragma unroll
    for (int i = 0; i < 4; i++) {
        int fid = tid + i * 256;
        int row = fid >> 3, kq = (fid & 7) * 4;
        int gm = bm + row, gk = k0 + kq;
        cp16(As + row * ASTRIDE + kq, A + (size_t)gm * lda + gk, gm < M && gk < K);
    }
}

__device__ __forceinline__ void loadB_nt(float* Bs, const float* B, int ldb,
                                         int bn, int k0, int N, int K, int tid) {
#pragma unroll
    for (int i = 0; i < 2; i++) {
        int fid = tid + i * 256;
        int row = fid >> 3, kq = (fid & 7) * 4;
        int gn = bn + row, gk = k0 + kq;
        cp16(Bs + row * 36 + kq, B + (size_t)gn * ldb + gk, gn < N && gk < K);
    }
}

__device__ __forceinline__ void loadB_nn(float* Bs, const float* B, int ldb,
                                         int bn, int k0, int N, int K, int tid) {
#pragma unroll
    for (int i = 0; i < 2; i++) {
        int fid = tid + i * 256;
        int kr = fid >> 4, nq = (fid & 15) * 4;
        int gk = k0 + kr, gn = bn + nq;
        cp16(Bs + kr * 72 + nq, B + (size_t)gk * ldb + gn, gk < K && gn < N);
    }
}

template <bool BT>
__device__ __forceinline__ void compute_stage(const float* As, const float* Bs,
                                              float acc[2][4][4],
                                              int wm, int wn, int g8, int t4) {
#pragma unroll
    for (int kb = 0; kb < 32; kb += 8) {
        unsigned a[2][4];
#pragma unroll
        for (int fm = 0; fm < 2; fm++) {
            int m0 = wm * 32 + fm * 16;
            a[fm][0] = __float_as_uint(As[(m0 + g8)     * ASTRIDE + kb + t4]);
            a[fm][1] = __float_as_uint(As[(m0 + 8 + g8) * ASTRIDE + kb + t4]);
            a[fm][2] = __float_as_uint(As[(m0 + g8)     * ASTRIDE + kb + t4 + 4]);
            a[fm][3] = __float_as_uint(As[(m0 + 8 + g8) * ASTRIDE + kb + t4 + 4]);
        }
#pragma unroll
        for (int fn = 0; fn < 4; fn++) {
            int n0 = wn * 32 + fn * 8;
            unsigned b0, b1;
            if (BT) {
                b0 = __float_as_uint(Bs[(n0 + g8) * 36 + kb + t4]);
                b1 = __float_as_uint(Bs[(n0 + g8) * 36 + kb + t4 + 4]);
            } else {
                b0 = __float_as_uint(Bs[(kb + t4)     * 72 + n0 + g8]);
                b1 = __float_as_uint(Bs[(kb + t4 + 4) * 72 + n0 + g8]);
            }
            mma8(acc[0][fn], a[0], b0, b1);
            mma8(acc[1][fn], a[1], b0, b1);
        }
    }
}

// EPI: 0 none, 1 relu(v*sc[col]+bi[col]), 2 relu(v*sc[row]+bi[row])
template <int EPI, bool BT>
__device__ __forceinline__ void tgemm_core(
    const float* __restrict__ A, int lda,
    const float* __restrict__ B, int ldb,
    float* __restrict__ C, int ldc,
    int M, int N, int K,
    const float* __restrict__ sc, const float* __restrict__ bi)
{
    extern __shared__ float sm[];
    float* As = sm;
    float* Bs = sm + STAGES * ASZ;
    int tid = threadIdx.x;
    int lane = tid & 31, wid = tid >> 5;
    int wm = wid & 3, wn = wid >> 2;
    int bm = blockIdx.y * 128, bn = blockIdx.x * 64;
    int g8 = lane >> 2, t4 = lane & 3;

    float acc[2][4][4];
#pragma unroll
    for (int i = 0; i < 2; i++)
#pragma unroll
        for (int j = 0; j < 4; j++)
#pragma unroll
            for (int q = 0; q < 4; q++) acc[i][j][q] = 0.f;

    int KT = (K + 31) / 32;

    // prologue: stages 0, 1
    loadA(As, A, lda, bm, 0, M, K, tid);
    if (BT) loadB_nt(Bs, B, ldb, bn, 0, N, K, tid);
    else    loadB_nn(Bs, B, ldb, bn, 0, N, K, tid);
    asm volatile("cp.async.commit_group;\n");
    if (KT > 1) {
        loadA(As + ASZ, A, lda, bm, 32, M, K, tid);
        if (BT) loadB_nt(Bs + BSZ, B, ldb, bn, 32, N, K, tid);
        else    loadB_nn(Bs + BSZ, B, ldb, bn, 32, N, K, tid);
    }
    asm volatile("cp.async.commit_group;\n");

    for (int kt = 0; kt < KT; kt++) {
        if (kt + 2 < KT) {
            int s = (kt + 2) % STAGES;
            int k0 = (kt + 2) * 32;
            loadA(As + s * ASZ, A, lda, bm, k0, M, K, tid);
            if (BT) loadB_nt(Bs + s * BSZ, B, ldb, bn, k0, N, K, tid);
            else    loadB_nn(Bs + s * BSZ, B, ldb, bn, k0, N, K, tid);
        }
        asm volatile("cp.async.commit_group;\n");
        asm volatile("cp.async.wait_group 2;\n");
        __syncthreads();
        int s = kt % STAGES;
        compute_stage<BT>(As + s * ASZ, Bs + s * BSZ, acc, wm, wn, g8, t4);
        __syncthreads();
    }

    // epilogue
#pragma unroll
    for (int fm = 0; fm < 2; fm++) {
#pragma unroll
        for (int fn = 0; fn < 4; fn++) {
            int gm0 = bm + wm * 32 + fm * 16 + g8;
            int gn0 = bn + wn * 32 + fn * 8 + 2 * t4;
#pragma unroll
            for (int h = 0; h < 2; h++) {
                int gm = gm0 + h * 8;
                if (gm >= M) continue;
#pragma unroll
                for (int q = 0; q < 2; q++) {
                    int gn = gn0 + q;
                    if (gn >= N) continue;
                    float v = acc[fm][fn][h * 2 + q];
                    if (EPI == 1) v = fmaxf(fmaf(v, sc[gn], bi[gn]), 0.f);
                    if (EPI == 2) v = fmaxf(fmaf(v, sc[gm], bi[gm]), 0.f);
                    C[(size_t)gm * ldc + gn] = v;
                }
            }
        }
    }
}

// dual-branch (blockIdx.z selects parameter set)
template <int EPI, bool BT>
__global__ void __launch_bounds__(256) tgemm_dual(
    const float* A0, const float* A1, int lda,
    const float* B0, const float* B1, int ldb,
    float* C0, float* C1, int ldc,
    int M, int N, int K,
    const float* sc0, const float* sc1,
    const float* bi0, const float* bi1)
{
    int z = blockIdx.z;
    tgemm_core<EPI, BT>(z ? A1 : A0, lda, z ? B1 : B0, ldb, z ? C1 : C0, ldc,
                        M, N, K, z ? sc1 : sc0, z ? bi1 : bi0);
}

// Batched attention aggregation (NN): out[r][c] = sum_q Att[n][r][q] * feat[q][c]
__global__ void __launch_bounds__(256) tgemm_agg() {
    int zb = blockIdx.z;
    int n = zb & 3, br = zb >> 2;
    const float* A = (br ? g_Ad : g_Ac) + (size_t)n * PPX * PPX;
    const float* B = g_xcd + (size_t)n * PPX * 1024 + br * 512;
    float* C = g_agg + (size_t)n * PPX * 1024 + br * 512;
    tgemm_core<0, false>(A, PPX, B, 1024, C, 1024, PPX, MIDC, PPX, nullptr, nullptr);
}

// ---------------- psa_mask gather + softmax ----------------
__global__ void softmax_collect(const float* __restrict__ yc, float* __restrict__ Ao) {
    int nr = blockIdx.x;
    int r = nr % PPX;
    int rh = r / OWW, rw = r % OWW;
    const float* row = yc + (size_t)nr * MMC;
    __shared__ float buf[PPX];
    __shared__ float red[256];
    int t = threadIdx.x;
    float mx = -1e30f;
    for (int q = t; q < PPX; q += 256) {
        int qh = q / OWW, qw = q % OWW;
        float v = row[(qh - rh + HALF) * 59 + (qw - rw + HALF)];
        buf[q] = v;
        mx = fmaxf(mx, v);
    }
    red[t] = mx; __syncthreads();
    for (int s = 128; s > 0; s >>= 1) { if (t < s) red[t] = fmaxf(red[t], red[t + s]); __syncthreads(); }
    mx = red[0]; __syncthreads();
    float sum = 0.f;
    for (int q = t; q < PPX; q += 256) {
        float e = __expf(buf[q] - mx);
        buf[q] = e; sum += e;
    }
    red[t] = sum; __syncthreads();
    for (int s = 128; s > 0; s >>= 1) { if (t < s) red[t] += red[t + s]; __syncthreads(); }
    float inv = 1.f / red[0];
    float* out = Ao + (size_t)nr * PPX;
    for (int q = t; q < PPX; q += 256) out[q] = buf[q] * inv;
}

__global__ void softmax_distribute(const float* __restrict__ yd, float* __restrict__ Ao) {
    int nr = blockIdx.x;
    int n = nr / PPX, r = nr % PPX;
    int rh = r / OWW, rw = r % OWW;
    __shared__ float buf[PPX];
    __shared__ float red[256];
    int t = threadIdx.x;
    float mx = -1e30f;
    for (int q = t; q < PPX; q += 256) {
        int qh = q / OWW, qw = q % OWW;
        float v = yd[(size_t)(n * PPX + q) * MMC + (rh - qh + HALF) * 59 + (rw - qw + HALF)];
        buf[q] = v;
        mx = fmaxf(mx, v);
    }
    red[t] = mx; __syncthreads();
    for (int s = 128; s > 0; s >>= 1) { if (t < s) red[t] = fmaxf(red[t], red[t + s]); __syncthreads(); }
    mx = red[0]; __syncthreads();
    float sum = 0.f;
    for (int q = t; q < PPX; q += 256) {
        float e = __expf(buf[q] - mx);
        buf[q] = e; sum += e;
    }
    red[t] = sum; __syncthreads();
    for (int s = 128; s > 0; s >>= 1) { if (t < s) red[t] += red[t + s]; __syncthreads(); }
    float inv = 1.f / red[0];
    float* out = Ao + (size_t)nr * PPX;
    for (int q = t; q < PPX; q += 256) out[q] = buf[q] * inv;
}

// ---------------- output assembly ----------------
__global__ void copy_x(const float* __restrict__ x, float* __restrict__ out) {
    size_t idx = (size_t)blockIdx.x * 256 + threadIdx.x;
    size_t total = (size_t)NB * C_IN * MMC;
    if (idx >= total) return;
    int s = idx % MMC;
    size_t nc = idx / MMC;
    int n = (int)(nc / C_IN), c = (int)(nc % C_IN);
    out[((size_t)(n * 4096 + c)) * MMC + s] = x[idx];
}

__global__ void upsample(float* __restrict__ out) {
    size_t idx = (size_t)blockIdx.x * 256 + threadIdx.x;
    size_t total = (size_t)NB * C_IN * MMC;
    if (idx >= total) return;
    int s = idx % MMC;
    size_t nc = idx / MMC;
    int n = (int)(nc / C_IN), c = (int)(nc % C_IN);
    int i = s / 59, j = s % 59;
    float fi = i * 0.5f, fj = j * 0.5f;
    int i0 = min(i >> 1, OHH - 2);
    int j0 = min(j >> 1, OWW - 2);
    float fh = fi - i0, fw = fj - j0;
    int i1 = i0 + 1, j1 = j0 + 1;
    const float* src = g_xpt + (size_t)c * MP + n * PPX;
    float v00 = src[i0 * OWW + j0], v01 = src[i0 * OWW + j1];
    float v10 = src[i1 * OWW + j0], v11 = src[i1 * OWW + j1];
    float v = (1.f - fh) * ((1.f - fw) * v00 + fw * v01)
            + fh * ((1.f - fw) * v10 + fw * v11);
    out[((size_t)(n * 4096 + 2048 + c)) * MMC + s] = v;
}

// ---------------- launch ----------------
extern "C" void kernel_launch(void* const* d_in, const int* in_sizes, int n_in,
                              void* d_out, int out_size) {
    const float* x    = (const float*)d_in[0];
    const float* rw   = (const float*)d_in[1];
    const float* rbn  = (const float*)d_in[2];
    const float* a1w  = (const float*)d_in[3];
    const float* abn  = (const float*)d_in[4];
    const float* a2w  = (const float*)d_in[5];
    const float* rpw  = (const float*)d_in[6];
    const float* rpbn = (const float*)d_in[7];
    const float* ap1w = (const float*)d_in[8];
    const float* apbn = (const float*)d_in[9];
    const float* ap2w = (const float*)d_in[10];
    const float* pjw  = (const float*)d_in[11];
    const float* pjbn = (const float*)d_in[12];
    float* out = (float*)d_out;

    float *xs, *xcd, *z, *yc, *yd, *Ac, *Ad, *agg, *xpt;
    float *s1, *t1, *s2, *t2, *s3, *t3;
    cudaGetSymbolAddress((void**)&xs,  g_xs);
    cudaGetSymbolAddress((void**)&xcd, g_xcd);
    cudaGetSymbolAddress((void**)&z,   g_z);
    cudaGetSymbolAddress((void**)&yc,  g_yc);
    cudaGetSymbolAddress((void**)&yd,  g_yd);
    cudaGetSymbolAddress((void**)&Ac,  g_Ac);
    cudaGetSymbolAddress((void**)&Ad,  g_Ad);
    cudaGetSymbolAddress((void**)&agg, g_agg);
    cudaGetSymbolAddress((void**)&xpt, g_xpt);
    cudaGetSymbolAddress((void**)&s1,  g_s1);
    cudaGetSymbolAddress((void**)&t1,  g_t1);
    cudaGetSymbolAddress((void**)&s2,  g_s2);
    cudaGetSymbolAddress((void**)&t2,  g_t2);
    cudaGetSymbolAddress((void**)&s3,  g_s3);
    cudaGetSymbolAddress((void**)&t3,  g_t3);

    // allow >48KB dynamic smem for GEMM kernels (idempotent host calls)
    cudaFuncSetAttribute(tgemm_dual<1, true>, cudaFuncAttributeMaxDynamicSharedMemorySize, SMEM_BYTES);
    cudaFuncSetAttribute(tgemm_dual<0, true>, cudaFuncAttributeMaxDynamicSharedMemorySize, SMEM_BYTES);
    cudaFuncSetAttribute(tgemm_dual<2, true>, cudaFuncAttributeMaxDynamicSharedMemorySize, SMEM_BYTES);
    cudaFuncSetAttribute(tgemm_agg,           cudaFuncAttributeMaxDynamicSharedMemorySize, SMEM_BYTES);

    // 1. BN folding
    bnprep<<<8, 256>>>(rbn, rpbn, abn, apbn, pjbn);

    // 2. subsample+transpose input
    gather_sub<<<dim3(NB * OHH, C_IN / 32), 256>>>(x);

    // 3. conv1 both branches in one launch (z=2)
    {
        dim3 g(MIDC / 64, (MP + 127) / 128, 2);
        tgemm_dual<1, true><<<g, 256, SMEM_BYTES>>>(
            xs, xs, C_IN, rw, rpw, C_IN, xcd, xcd + 512, 1024,
            MP, MIDC, C_IN, s1, s1 + 512, t1, t1 + 512);
    }

    // 4. attention conv1 both branches (z=2)
    {
        dim3 g(MIDC / 64, (MP + 127) / 128, 2);
        tgemm_dual<1, true><<<g, 256, SMEM_BYTES>>>(
            xcd, xcd + 512, 1024, a1w, ap1w, MIDC, z, z + 512, 1024,
            MP, MIDC, MIDC, s2, s2 + 512, t2, t2 + 512);
    }

    // 5. attention conv2 (logits) both branches (z=2)
    {
        dim3 g((MMC + 63) / 64, (MP + 127) / 128, 2);
        tgemm_dual<0, true><<<g, 256, SMEM_BYTES>>>(
            z, z + 512, 1024, a2w, ap2w, MIDC, yc, yd, MMC,
            MP, MMC, MIDC, nullptr, nullptr, nullptr, nullptr);
    }

    // 6. psa_mask gather + softmax
    softmax_collect<<<MP, 256>>>(yc, Ac);
    softmax_distribute<<<MP, 256>>>(yd, Ad);

    // 7. aggregation (batched over n x branch), NN, K=900
    {
        dim3 g(MIDC / 64, (PPX + 127) / 128, 8);
        tgemm_agg<<<g, 256, SMEM_BYTES>>>();
    }

    // 8. projection: pjw[2048,1024] x agg[3600,1024]^T -> xpt [2048][3600]
    {
        dim3 g((MP + 63) / 64, C_IN / 128, 1);
        tgemm_dual<2, true><<<g, 256, SMEM_BYTES>>>(
            pjw, pjw, 1024, agg, agg, 1024, xpt, xpt, MP,
            C_IN, MP, 1024, s3, s3, t3, t3);
    }

    // 9. assemble output
    {
        size_t total = (size_t)NB * C_IN * MMC;
        int blocks = (int)((total + 255) / 256);
        copy_x<<<blocks, 256>>>(x, out);
        upsample<<<blocks, 256>>>(out);
    }
}